// round 3
// baseline (speedup 1.0000x reference)
#include <cuda_runtime.h>
#include <math.h>

#define NB   36
#define NB2  72
#define SS   7
#define NOUT (2*NB + 2)   // 74

// One block per batch b. 512 threads.
// Work item w = tid>>1 in [0,252): s = w/36, k = w%36. Lane pair h = tid&1
// splits the 36-term reductions in half (18 each), combined via shfl_xor(1).
// Shared rows padded to s=8 so lanes with w in [252,256) can run the loops
// harmlessly (writes are guarded) and warp-uniform shfl masks stay legal.
__global__ __launch_bounds__(512, 2)
void deepwarping_kernel(const float* __restrict__ ll1,   // [B,S,NB]
                        const float* __restrict__ ll2,   // [B,S,NB]
                        const float* __restrict__ inp,   // [B,S,NB]
                        const float* __restrict__ yaw,   // [B]
                        const float* __restrict__ T,     // [61,NB,NB]
                        const float* __restrict__ M,     // [NB,NB]
                        const float* __restrict__ pop,   // [2,NB]
                        float* __restrict__ out)         // [B,S,NOUT]
{
    const int b   = blockIdx.x;
    const int tid = threadIdx.x;

    __shared__ float seMd[NB * NB2];     // exp(M) rows doubled: [i][c], c=0..71, c%36
    __shared__ float sTt [NB * NB];      // transposed transform: sTt[j*36+k] = T[idx][k][j]
    __shared__ float se1 [8][NB];        // exp(ll1)
    __shared__ float se2d[8][NB2];       // exp(ll2) doubled
    __shared__ float si  [8][NB];        // inp
    __shared__ float ssum[8][NB];        // s_k
    __shared__ float spop[2 * NB];

    // yaw -> transform index (offset 30; rintf = round-half-even = jnp.round)
    const int idx = 30 + (int)rintf(yaw[b] * (180.0f / 3.14159265358979323846f));
    const int base = b * SS * NB;

    // ---- staging (512 threads) ----
    // exp(M) doubled rows: 2592 elements
    for (int t = tid; t < NB * NB2; t += 512) {
        int i = t / NB2, c = t % NB2;
        seMd[t] = __expf(M[i * NB + (c >= NB ? c - NB : c)]);
    }
    // transposed T row-block: read linear (coalesced), write transposed
    {
        const float* Tb = T + idx * NB * NB;
        for (int t = tid; t < NB * NB; t += 512) {
            int k = t / NB, j = t % NB;
            sTt[j * NB + k] = Tb[t];
        }
    }
    // exp(ll2) doubled: 504 elements
    if (tid < SS * NB2) {
        int s = tid / NB2, c = tid % NB2;
        se2d[s][c] = __expf(ll2[base + s * NB + (c >= NB ? c - NB : c)]);
    }
    // exp(ll1), inp: 252 each
    if (tid < SS * NB) {
        (&se1[0][0])[ (tid/NB)* NB + tid%NB ] = __expf(ll1[base + tid]);
        (&si [0][0])[ (tid/NB)* NB + tid%NB ] = inp[base + tid];
    }
    if (tid < 2 * NB) spop[tid] = pop[tid];
    __syncthreads();

    const int w = tid >> 1;          // work item
    const int h = tid & 1;           // half
    const int s = (w < 252) ? (w / NB) : 7;   // s=7 -> padded rows (garbage, unwritten)
    const int k = w % NB;
    const int i0 = h * 18;

    // s_k partial: sum over 18 i's of e1[i]*e2[(i+k)]*eM[i][(i+k)] (doubled rows, no wrap)
    float acc = 0.0f;
    #pragma unroll
    for (int ii = 0; ii < 18; ii++) {
        const int i = i0 + ii;
        acc += se1[s][i] * (se2d[s][i + k] * seMd[i * NB2 + i + k]);
    }
    acc += __shfl_xor_sync(0xFFFFFFFFu, acc, 1);   // both lanes hold full s_k

    // matvec partial: warped[k] = sum_j T[k][j]*inp[j]
    float wv = 0.0f;
    #pragma unroll
    for (int jj = 0; jj < 18; jj++) {
        const int j = i0 + jj;
        wv += sTt[j * NB + k] * si[s][j];
    }
    wv += __shfl_xor_sync(0xFFFFFFFFu, wv, 1);

    if (w < 252 && h == 0) ssum[s][k] = acc;
    __syncthreads();

    if (w < 252) {
        // tot = sum_k ssum[s][k], 4-way accumulator tree (short dep chain)
        float t0 = 0.f, t1 = 0.f, t2 = 0.f, t3 = 0.f;
        #pragma unroll
        for (int kk = 0; kk < NB; kk += 4) {
            t0 += ssum[s][kk];
            t1 += ssum[s][kk + 1];
            t2 += ssum[s][kk + 2];
            t3 += ssum[s][kk + 3];
        }
        const float tot = (t0 + t1) + (t2 + t3);

        float* o = out + (b * SS + s) * NOUT;
        if (h == 0) {
            o[k]          = wv;
            o[NB + 2 + k] = __logf(acc) - __logf(tot);
        } else if (k == 0) {
            // population vector, one lane per s
            const float inv = 1.0f / tot;
            float v0 = 0.f, v1 = 0.f;
            #pragma unroll
            for (int kk = 0; kk < NB; kk++) {
                const float p = ssum[s][kk] * inv;
                v0 += p * spop[kk];
                v1 += p * spop[NB + kk];
            }
            v0 += 1e-8f;
            const float n = sqrtf(v0 * v0 + v1 * v1);
            v0 /= n; v1 /= n;
            o[NB]     = fminf(fmaxf(v0, -1.0f), 1.0f);
            o[NB + 1] = fminf(fmaxf(v1, -1.0f), 1.0f);
        }
    }
}

extern "C" void kernel_launch(void* const* d_in, const int* in_sizes, int n_in,
                              void* d_out, int out_size)
{
    const float* ll1 = (const float*)d_in[0];   // loglikelihood1 [128,7,36]
    const float* ll2 = (const float*)d_in[1];   // loglikelihood2 [128,7,36]
    const float* inp = (const float*)d_in[2];   // inp            [128,7,36]
    const float* yaw = (const float*)d_in[3];   // yaw            [128]
    const float* T   = (const float*)d_in[4];   // transform_matrices [61,36,36]
    const float* M   = (const float*)d_in[5];   // logprior_rotate_matrix [36,36]
    // d_in[6] = template_log — equivalent to k=(j-i)%36 selector; unused
    const float* pop = (const float*)d_in[7];   // population_vector [2,36]
    float* out = (float*)d_out;

    const int B = in_sizes[3];                  // 128
    deepwarping_kernel<<<B, 512>>>(ll1, ll2, inp, yaw, T, M, pop, out);
}

// round 4
// speedup vs baseline: 1.2844x; 1.2844x over previous
#include <cuda_runtime.h>
#include <math.h>

#define NB 36
#define SS 7
#define NOUT (2*NB + 2)   // 74

// One block per batch b, 256 threads. Thread t<252: (s=t/36, k=t%36).
// Staging fully vectorized (float4) to shorten the pre-barrier LDG chain.
__global__ __launch_bounds__(256, 4)
void deepwarping_kernel(const float* __restrict__ ll1,   // [B,S,NB]
                        const float* __restrict__ ll2,   // [B,S,NB]
                        const float* __restrict__ inp,   // [B,S,NB]
                        const float* __restrict__ yaw,   // [B]
                        const float* __restrict__ T,     // [61,NB,NB]
                        const float* __restrict__ M,     // [NB,NB]
                        const float* __restrict__ pop,   // [2,NB]
                        float* __restrict__ out)         // [B,S,NOUT]
{
    const int b   = blockIdx.x;
    const int tid = threadIdx.x;

    __shared__ float seM [NB * NB];     // exp(M)
    __shared__ float sT  [NB * NB];     // yaw-selected transform matrix (row-major)
    __shared__ float se1 [SS * NB];     // exp(ll1)
    __shared__ float se2 [SS * NB];     // exp(ll2)
    __shared__ float si  [SS * NB];     // inp
    __shared__ float ssum[SS][NB];      // s_k
    __shared__ float spop[2 * NB];

    // yaw -> transform index (offset 30; rintf = round-half-even = jnp.round)
    const int idx  = 30 + (int)rintf(yaw[b] * (180.0f / 3.14159265358979323846f));
    const int base = b * SS * NB;       // multiple of 4 -> float4-aligned

    // ---- staging, all float4 ----
    {   // exp(M): 324 float4
        const float4* M4 = (const float4*)M;
        #pragma unroll
        for (int t = tid; t < (NB * NB) / 4; t += 256) {
            float4 v = M4[t];
            ((float4*)seM)[t] = make_float4(__expf(v.x), __expf(v.y),
                                            __expf(v.z), __expf(v.w));
        }
    }
    {   // T[idx] row-block: 324 float4 straight copy
        const float4* T4 = (const float4*)(T + idx * NB * NB);
        #pragma unroll
        for (int t = tid; t < (NB * NB) / 4; t += 256) {
            ((float4*)sT)[t] = T4[t];
        }
    }
    if (tid < (SS * NB) / 4) {          // 63 float4 per tensor
        float4 a = ((const float4*)(ll1 + base))[tid];
        float4 c = ((const float4*)(ll2 + base))[tid];
        float4 d = ((const float4*)(inp + base))[tid];
        ((float4*)se1)[tid] = make_float4(__expf(a.x), __expf(a.y), __expf(a.z), __expf(a.w));
        ((float4*)se2)[tid] = make_float4(__expf(c.x), __expf(c.y), __expf(c.z), __expf(c.w));
        ((float4*)si )[tid] = d;
    }
    if (tid >= 64 && tid < 64 + (2 * NB) / 4) {   // 18 float4, separate warp from above
        ((float4*)spop)[tid - 64] = ((const float4*)pop)[tid - 64];
    }
    __syncthreads();

    const int s  = tid / NB;            // valid when tid < 252
    const int k  = tid % NB;
    const int sb = s * NB;

    float acc = 0.0f;
    if (tid < SS * NB) {
        // s_k = sum_i e1[i] * e2[(i+k)%36] * eM[i][(i+k)%36], 4 accumulators
        float a0 = 0.f, a1 = 0.f, a2 = 0.f, a3 = 0.f;
        #pragma unroll
        for (int i = 0; i < NB; i += 4) {
            int j0 = i + k;     if (j0 >= NB) j0 -= NB;
            int j1 = i + 1 + k; if (j1 >= NB) j1 -= NB;
            int j2 = i + 2 + k; if (j2 >= NB) j2 -= NB;
            int j3 = i + 3 + k; if (j3 >= NB) j3 -= NB;
            a0 += se1[sb + i    ] * (se2[sb + j0] * seM[(i    ) * NB + j0]);
            a1 += se1[sb + i + 1] * (se2[sb + j1] * seM[(i + 1) * NB + j1]);
            a2 += se1[sb + i + 2] * (se2[sb + j2] * seM[(i + 2) * NB + j2]);
            a3 += se1[sb + i + 3] * (se2[sb + j3] * seM[(i + 3) * NB + j3]);
        }
        acc = (a0 + a1) + (a2 + a3);
        ssum[s][k] = acc;
    }
    __syncthreads();

    if (tid < SS * NB) {
        // tot: 4-way accumulator tree over broadcast LDS
        float t0 = 0.f, t1 = 0.f, t2 = 0.f, t3 = 0.f;
        #pragma unroll
        for (int kk = 0; kk < NB; kk += 4) {
            t0 += ssum[s][kk];
            t1 += ssum[s][kk + 1];
            t2 += ssum[s][kk + 2];
            t3 += ssum[s][kk + 3];
        }
        const float tot = (t0 + t1) + (t2 + t3);

        // warped[k] = sum_j T[k][j] * inp[j], 4 accumulators
        float w0 = 0.f, w1 = 0.f, w2 = 0.f, w3 = 0.f;
        const int kb = k * NB;
        #pragma unroll
        for (int j = 0; j < NB; j += 4) {
            w0 += sT[kb + j    ] * si[sb + j    ];
            w1 += sT[kb + j + 1] * si[sb + j + 1];
            w2 += sT[kb + j + 2] * si[sb + j + 2];
            w3 += sT[kb + j + 3] * si[sb + j + 3];
        }
        const float w = (w0 + w1) + (w2 + w3);

        float* o = out + (b * SS + s) * NOUT;
        o[k]          = w;
        o[NB + 2 + k] = __logf(acc) - __logf(tot);

        if (k == 0) {
            const float inv = 1.0f / tot;
            float v0 = 0.f, v1 = 0.f;
            #pragma unroll
            for (int kk = 0; kk < NB; kk++) {
                const float p = ssum[s][kk] * inv;
                v0 += p * spop[kk];
                v1 += p * spop[NB + kk];
            }
            v0 += 1e-8f;
            const float n = sqrtf(v0 * v0 + v1 * v1);
            v0 /= n; v1 /= n;
            o[NB]     = fminf(fmaxf(v0, -1.0f), 1.0f);
            o[NB + 1] = fminf(fmaxf(v1, -1.0f), 1.0f);
        }
    }
}

extern "C" void kernel_launch(void* const* d_in, const int* in_sizes, int n_in,
                              void* d_out, int out_size)
{
    const float* ll1 = (const float*)d_in[0];   // loglikelihood1 [128,7,36]
    const float* ll2 = (const float*)d_in[1];   // loglikelihood2 [128,7,36]
    const float* inp = (const float*)d_in[2];   // inp            [128,7,36]
    const float* yaw = (const float*)d_in[3];   // yaw            [128]
    const float* T   = (const float*)d_in[4];   // transform_matrices [61,36,36]
    const float* M   = (const float*)d_in[5];   // logprior_rotate_matrix [36,36]
    // d_in[6] = template_log — equivalent to k=(j-i)%36 selector; unused
    const float* pop = (const float*)d_in[7];   // population_vector [2,36]
    float* out = (float*)d_out;

    const int B = in_sizes[3];                  // 128
    deepwarping_kernel<<<B, 256>>>(ll1, ll2, inp, yaw, T, M, pop, out);
}